// round 2
// baseline (speedup 1.0000x reference)
#include <cuda_runtime.h>
#include <math.h>

#define BB   128          // batch
#define NKG  500          // KG vertices
#define NN   502          // total nodes
#define DD   1024         // embed dim
#define HH   256          // hidden
#define EE   4000         // edges
#define NBTOT (BB*NN)     // 64256

// ---------------------------------------------------------------------------
// Scratch (single __device__ symbol; all loops bounded by runtime m)
// ---------------------------------------------------------------------------
struct __align__(16) Scratch {
    float hbase[NKG*HH];
    float hsens[BB*HH];
    float zb1[NN*HH], zb2[NN*HH];
    float g2b[NN*HH], g3b[NN*HH];
    float a1[NN*HH], a2[NN*HH], a3[NN*HH];
    float d1 [BB*NN*HH];
    float g2d[BB*NN*HH];
    float dy2[BB*NN*HH];
    float d2 [BB*NN*HH];
    float g3d[BB*NN*HH];
    float dy3[BB*NN*HH];
    float csr_norm[EE];
    float c[NN], dinv[NN];
    float accA[3][HH], accAsq[3][HH], accD[3][HH], accDsq[3][HH], accAD[3][HH];
    float accS[HH], accS2[HH], accAc[HH];
    float sc[3][HH], sh[3][HH];
    int   csr_src[EE];
    int   cnt[NN], cur[NN], off[NN+1];
    int   slot1[NN], slot2[NN], slot3[NN];
    int   list1[NN], list2[NN], list3[NN];
    int   mark2[NN], mark3[NN];
    int   m1, m2, m3;
};
__device__ Scratch S;

__device__ __forceinline__ float elu_f(float x) { return x > 0.f ? x : expm1f(x); }
__device__ __forceinline__ int clampn(int v) { return v < 0 ? 0 : (v >= NN ? NN - 1 : v); }

// ---------------------------------------------------------------------------
// init / graph preprocessing    (edge_index is int32: JAX x64 disabled)
// ---------------------------------------------------------------------------
__global__ void k_init(Scratch* s) {
    int t = blockIdx.x * 256 + threadIdx.x;
    if (t < NN) { s->cnt[t] = 0; s->cur[t] = 0; s->mark2[t] = 0; s->mark3[t] = 0; }
    if (t < HH) {
        for (int l = 0; l < 3; l++) {
            s->accA[l][t] = 0.f; s->accAsq[l][t] = 0.f;
            s->accD[l][t] = 0.f; s->accDsq[l][t] = 0.f; s->accAD[l][t] = 0.f;
        }
        s->accS[t] = 0.f; s->accS2[t] = 0.f; s->accAc[t] = 0.f;
    }
}

__global__ void k_count(Scratch* s, const int* __restrict__ ei) {
    int e = blockIdx.x * 256 + threadIdx.x;
    if (e < EE) atomicAdd(&s->cnt[clampn(ei[EE + e])], 1);
}

__global__ void k_scan(Scratch* s) {
    __shared__ int sm[512];
    int t = threadIdx.x;
    int v = (t < NN) ? s->cnt[t] : 0;
    if (t < NN) s->dinv[t] = rsqrtf((float)(v + 1));   // +1 self loop
    sm[t] = v; __syncthreads();
    for (int d = 1; d < 512; d <<= 1) {
        int x = (t >= d) ? sm[t - d] : 0; __syncthreads();
        sm[t] += x; __syncthreads();
    }
    if (t < NN) s->off[t] = sm[t] - v;
    if (t == NN - 1) s->off[NN] = sm[t];
}

__global__ void k_fill(Scratch* s, const int* __restrict__ ei) {
    int e = blockIdx.x * 256 + threadIdx.x;
    if (e >= EE) return;
    int src = clampn(ei[e]), dst = clampn(ei[EE + e]);
    int p = s->off[dst] + atomicAdd(&s->cur[dst], 1);
    s->csr_src[p] = src;
    s->csr_norm[p] = s->dinv[src] * s->dinv[dst];
}

// ---------------------------------------------------------------------------
// fp32 tiled GEMM: C[M,256] = A[M,K] @ W[K,256]. If mptr: M = *mptr * mmul.
// ---------------------------------------------------------------------------
__global__ void k_gemm(const float* __restrict__ A, const float* __restrict__ W,
                       float* __restrict__ C, int K, int M,
                       const int* __restrict__ mptr, int mmul) {
    if (mptr) M = (*mptr) * mmul;
    int rb = blockIdx.x * 64;
    if (rb >= M) return;
    int cb = blockIdx.y * 64;
    __shared__ __align__(16) float As[16][64];
    __shared__ __align__(16) float Ws[16][64];
    int tid = threadIdx.x;
    int tm = (tid >> 4) << 2;
    int tn = (tid & 15) << 2;
    int r  = tid >> 2, kk = (tid & 3) << 2;
    int wr = tid >> 4, wc = (tid & 15) << 2;
    float acc[4][4] = {};
    for (int k0 = 0; k0 < K; k0 += 16) {
        float4 av = make_float4(0.f, 0.f, 0.f, 0.f);
        if (rb + r < M) av = *(const float4*)(A + (size_t)(rb + r) * K + k0 + kk);
        As[kk][r] = av.x; As[kk+1][r] = av.y; As[kk+2][r] = av.z; As[kk+3][r] = av.w;
        *(float4*)&Ws[wr][wc] = *(const float4*)(W + (size_t)(k0 + wr) * HH + cb + wc);
        __syncthreads();
#pragma unroll
        for (int q = 0; q < 16; q++) {
            float4 bv = *(const float4*)&Ws[q][tn];
            float a0 = As[q][tm], a1 = As[q][tm+1], a2 = As[q][tm+2], a3 = As[q][tm+3];
            acc[0][0] += a0*bv.x; acc[0][1] += a0*bv.y; acc[0][2] += a0*bv.z; acc[0][3] += a0*bv.w;
            acc[1][0] += a1*bv.x; acc[1][1] += a1*bv.y; acc[1][2] += a1*bv.z; acc[1][3] += a1*bv.w;
            acc[2][0] += a2*bv.x; acc[2][1] += a2*bv.y; acc[2][2] += a2*bv.z; acc[2][3] += a2*bv.w;
            acc[3][0] += a3*bv.x; acc[3][1] += a3*bv.y; acc[3][2] += a3*bv.z; acc[3][3] += a3*bv.w;
        }
        __syncthreads();
    }
#pragma unroll
    for (int i = 0; i < 4; i++) {
        int row = rb + tm + i;
        if (row < M)
            *(float4*)(C + (size_t)row * HH + cb + tn) =
                make_float4(acc[i][0], acc[i][1], acc[i][2], acc[i][3]);
    }
}

// ---------------------------------------------------------------------------
// layer 1: batch-independent aggregate a1 (bias folded) + rank-1 coeffs c[n]
// ---------------------------------------------------------------------------
__global__ void k_agg1(Scratch* s, const float* __restrict__ b1) {
    int n = blockIdx.x, h = threadIdx.x;
    int e0 = s->off[n], e1 = s->off[n + 1];
    float acc = b1[h];
    for (int e = e0; e < e1; e++) {
        int src = s->csr_src[e];
        if (src < NKG) acc += s->csr_norm[e] * s->hbase[src * HH + h];
    }
    float di = s->dinv[n];
    if (n < NKG) acc += di * di * s->hbase[n * HH + h];   // self loop
    s->a1[n * HH + h] = acc;
    if (h == 0) {
        float cc = (n == NKG) ? di * di : 0.f;
        for (int e = e0; e < e1; e++)
            if (s->csr_src[e] == NKG) cc += s->csr_norm[e];
        s->c[n] = cc;
    }
}

// deterministic compaction of batch-dependent node sets
__global__ void k_compact(Scratch* s, int layer) {
    __shared__ int sm[512];
    int t = threadIdx.x;
    int f = 0;
    if (t < NN) {
        if (layer == 1)      f = (s->c[t] > 0.f) ? 1 : 0;
        else if (layer == 2) f = (s->mark2[t] | (s->slot1[t] >= 0)) ? 1 : 0;
        else                 f = (s->mark3[t] | (s->slot2[t] >= 0)) ? 1 : 0;
    }
    sm[t] = f; __syncthreads();
    for (int d = 1; d < 512; d <<= 1) {
        int x = (t >= d) ? sm[t - d] : 0; __syncthreads();
        sm[t] += x; __syncthreads();
    }
    int incl = sm[t];
    int* slot = (layer == 1) ? s->slot1 : (layer == 2) ? s->slot2 : s->slot3;
    int* list = (layer == 1) ? s->list1 : (layer == 2) ? s->list2 : s->list3;
    if (t < NN) {
        slot[t] = f ? (incl - 1) : -1;
        if (f) list[incl - 1] = t;
    }
    if (t == 511) {
        if (layer == 1)      s->m1 = incl;
        else if (layer == 2) s->m2 = incl;
        else                 s->m3 = incl;
    }
}

// ---------------------------------------------------------------------------
// BN statistics
// ---------------------------------------------------------------------------
__global__ void k_stats1(Scratch* s) {
    int h = threadIdx.x, bb = blockIdx.x;
    if (bb < 8) {
        float sA = 0.f, sA2 = 0.f, sAc = 0.f;
        for (int n = bb; n < NN; n += 8) {
            float A = s->a1[n * HH + h], cc = s->c[n];
            sA += A; sA2 += A * A; sAc += A * cc;
        }
        atomicAdd(&s->accA[0][h], sA);
        atomicAdd(&s->accAsq[0][h], sA2);
        atomicAdd(&s->accAc[h], sAc);
    } else {
        int k = bb - 8;
        float ss = 0.f, ss2 = 0.f;
        for (int b = k; b < BB; b += 2) {
            float v = s->hsens[b * HH + h];
            ss += v; ss2 += v * v;
        }
        atomicAdd(&s->accS[h], ss);
        atomicAdd(&s->accS2[h], ss2);
    }
}

__global__ void k_fin1(Scratch* s, const float* __restrict__ gamma,
                       const float* __restrict__ beta) {
    __shared__ float r1[256], r2[256];
    int h = threadIdx.x;
    float lc = 0.f, lc2 = 0.f;
    for (int n = h; n < NN; n += 256) { float cc = s->c[n]; lc += cc; lc2 += cc * cc; }
    r1[h] = lc; r2[h] = lc2; __syncthreads();
    for (int d = 128; d > 0; d >>= 1) {
        if (h < d) { r1[h] += r1[h + d]; r2[h] += r2[h + d]; }
        __syncthreads();
    }
    float Ec  = r1[0] / NN, Ec2 = r2[0] / NN;
    float EA  = s->accA[0][h] / NN, EA2 = s->accAsq[0][h] / NN, EAc = s->accAc[h] / NN;
    float Es  = s->accS[h] / BB,  Es2 = s->accS2[h] / BB;
    float mu  = EA + Ec * Es;
    float ey2 = EA2 + 2.f * EAc * Es + Ec2 * Es2;
    float rstd = rsqrtf(ey2 - mu * mu + 1e-5f);
    float scv = rstd * gamma[h];
    s->sc[0][h] = scv; s->sh[0][h] = beta[h] - mu * scv;
}

__global__ void k_statsA(Scratch* s, int layer) {
    int h = threadIdx.x, L = layer - 1;
    const float* a = (layer == 2) ? s->a2 : s->a3;
    float sA = 0.f, sA2 = 0.f;
    for (int n = blockIdx.x; n < NN; n += gridDim.x) {
        float v = a[n * HH + h]; sA += v; sA2 += v * v;
    }
    atomicAdd(&s->accA[L][h], sA);
    atomicAdd(&s->accAsq[L][h], sA2);
}

__global__ void k_statsD(Scratch* s, int layer) {
    int h = threadIdx.x, L = layer - 1;
    int m = (layer == 2) ? s->m2 : s->m3;
    const float* a  = (layer == 2) ? s->a2 : s->a3;
    const float* dy = (layer == 2) ? s->dy2 : s->dy3;
    const int* list = (layer == 2) ? s->list2 : s->list3;
    int R = BB * m;
    float sd = 0.f, sd2 = 0.f, sad = 0.f;
    for (int r = blockIdx.x; r < R; r += gridDim.x) {
        int j = r % m;
        float dv = dy[(size_t)r * HH + h];
        float A  = a[list[j] * HH + h];
        sd += dv; sd2 += dv * dv; sad += A * dv;
    }
    atomicAdd(&s->accD[L][h], sd);
    atomicAdd(&s->accDsq[L][h], sd2);
    atomicAdd(&s->accAD[L][h], sad);
}

__global__ void k_fin23(Scratch* s, const float* __restrict__ gamma,
                        const float* __restrict__ beta, int layer) {
    int h = threadIdx.x, L = layer - 1;
    float mu  = (BB * s->accA[L][h] + s->accD[L][h]) * (1.f / NBTOT);
    float ey2 = (BB * s->accAsq[L][h] + 2.f * s->accAD[L][h] + s->accDsq[L][h]) * (1.f / NBTOT);
    float rstd = rsqrtf(ey2 - mu * mu + 1e-5f);
    float scv = rstd * gamma[h];
    s->sc[L][h] = scv; s->sh[L][h] = beta[h] - mu * scv;
}

// ---------------------------------------------------------------------------
// BN+ELU materialization (base rows, zeroed on S; dep rows dense [B, m, H])
// ---------------------------------------------------------------------------
__global__ void k_zb(Scratch* s, int layer) {
    int n = blockIdx.x, h = threadIdx.x, L = layer - 1;
    const float* a  = (layer == 1) ? s->a1 : s->a2;
    const int* slot = (layer == 1) ? s->slot1 : s->slot2;
    float* zb       = (layer == 1) ? s->zb1 : s->zb2;
    float v = (slot[n] >= 0) ? 0.f : elu_f(a[n * HH + h] * s->sc[L][h] + s->sh[L][h]);
    zb[n * HH + h] = v;
}

__global__ void k_d1(Scratch* s) {
    int b = blockIdx.x, h = threadIdx.x;
    int m = s->m1;
    float sv = s->hsens[b * HH + h];
    float scv = s->sc[0][h], shv = s->sh[0][h];
    for (int j = blockIdx.y; j < m; j += gridDim.y) {
        int n = s->list1[j];
        float v = (s->a1[n * HH + h] + s->c[n] * sv) * scv + shv;
        s->d1[((size_t)b * m + j) * HH + h] = elu_f(v);
    }
}

__global__ void k_d2(Scratch* s) {
    int b = blockIdx.x, h = threadIdx.x;
    int m = s->m2;
    float scv = s->sc[1][h], shv = s->sh[1][h];
    for (int j = blockIdx.y; j < m; j += gridDim.y) {
        int n = s->list2[j];
        float v = (s->a2[n * HH + h] + s->dy2[((size_t)b * m + j) * HH + h]) * scv + shv;
        s->d2[((size_t)b * m + j) * HH + h] = elu_f(v);
    }
}

// mark dst nodes reached from previous batch-dependent set
__global__ void k_mark(Scratch* s, const int* __restrict__ ei, int layer) {
    int e = blockIdx.x * 256 + threadIdx.x;
    if (e >= EE) return;
    int src = clampn(ei[e]), dst = clampn(ei[EE + e]);
    const int* ps = (layer == 2) ? s->slot1 : s->slot2;
    int* mk       = (layer == 2) ? s->mark2 : s->mark3;
    if (ps[src] >= 0) mk[dst] = 1;
}

// base aggregation layers 2/3 (bias folded)
__global__ void k_aggb(Scratch* s, const float* __restrict__ bias, int layer) {
    int n = blockIdx.x, h = threadIdx.x;
    const float* g = (layer == 2) ? s->g2b : s->g3b;
    float di = s->dinv[n];
    float acc = bias[h] + di * di * g[n * HH + h];
    int e1 = s->off[n + 1];
    for (int e = s->off[n]; e < e1; e++)
        acc += s->csr_norm[e] * g[s->csr_src[e] * HH + h];
    ((layer == 2) ? s->a2 : s->a3)[n * HH + h] = acc;
}

// dep aggregation layers 2/3
__global__ void k_aggd(Scratch* s, int layer) {
    int b = blockIdx.x, h = threadIdx.x;
    int m  = (layer == 2) ? s->m2 : s->m3;
    int mp = (layer == 2) ? s->m1 : s->m2;
    const int* list  = (layer == 2) ? s->list2 : s->list3;
    const int* pslot = (layer == 2) ? s->slot1 : s->slot2;
    const float* g   = (layer == 2) ? s->g2d : s->g3d;
    float* dy        = (layer == 2) ? s->dy2 : s->dy3;
    for (int j = blockIdx.y; j < m; j += gridDim.y) {
        int n = list[j];
        float acc = 0.f;
        int sl = pslot[n];
        float di = s->dinv[n];
        if (sl >= 0) acc += di * di * g[((size_t)b * mp + sl) * HH + h];
        int e1 = s->off[n + 1];
        for (int e = s->off[n]; e < e1; e++) {
            int sp = pslot[s->csr_src[e]];
            if (sp >= 0) acc += s->csr_norm[e] * g[((size_t)b * mp + sp) * HH + h];
        }
        dy[((size_t)b * m + j) * HH + h] = acc;
    }
}

// final output: elu(bn3(a3 + dy3))
__global__ void k_out(Scratch* s, float* __restrict__ out) {
    int n = blockIdx.x, b = blockIdx.y, h = threadIdx.x;
    float v = s->a3[n * HH + h];
    int sl = s->slot3[n];
    if (sl >= 0) v += s->dy3[((size_t)b * s->m3 + sl) * HH + h];
    v = v * s->sc[2][h] + s->sh[2][h];
    out[((size_t)b * NN + n) * HH + h] = elu_f(v);
}

// ---------------------------------------------------------------------------
// launch
// ---------------------------------------------------------------------------
extern "C" void kernel_launch(void* const* d_in, const int* in_sizes, int n_in,
                              void* d_out, int out_size) {
    const float* sensor = (const float*)d_in[0];
    const float* basev  = (const float*)d_in[1];
    const int* ei       = (const int*)d_in[2];     // int32 (JAX x64 disabled)
    const float* W1 = (const float*)d_in[3];  const float* b1 = (const float*)d_in[4];
    const float* g1 = (const float*)d_in[5];  const float* be1 = (const float*)d_in[6];
    const float* W2 = (const float*)d_in[7];  const float* b2 = (const float*)d_in[8];
    const float* g2 = (const float*)d_in[9];  const float* be2 = (const float*)d_in[10];
    const float* W3 = (const float*)d_in[11]; const float* b3 = (const float*)d_in[12];
    const float* g3 = (const float*)d_in[13]; const float* be3 = (const float*)d_in[14];

    void* sp = nullptr;
    cudaGetSymbolAddress(&sp, S);
    Scratch* s = (Scratch*)sp;

    const int EBLK = (EE + 255) / 256;
    const int GBIG = (BB * NN + 63) / 64;   // row blocks upper bound for dep GEMMs

    k_init<<<2, 256>>>(s);
    k_count<<<EBLK, 256>>>(s, ei);
    k_scan<<<1, 512>>>(s);
    k_fill<<<EBLK, 256>>>(s, ei);

    // layer 1 (rank-1 in batch)
    k_gemm<<<dim3(8, 4), 256>>>(basev, W1, s->hbase, DD, NKG, nullptr, 0);
    k_gemm<<<dim3(2, 4), 256>>>(sensor, W1, s->hsens, DD, BB, nullptr, 0);
    k_agg1<<<NN, HH>>>(s, b1);
    k_compact<<<1, 512>>>(s, 1);
    k_stats1<<<10, 256>>>(s);
    k_fin1<<<1, 256>>>(s, g1, be1);
    k_zb<<<NN, HH>>>(s, 1);
    k_d1<<<dim3(BB, 4), HH>>>(s);

    // layer 2
    k_gemm<<<dim3(8, 4), 256>>>(s->zb1, W2, s->g2b, HH, NN, nullptr, 0);
    k_gemm<<<dim3(GBIG, 4), 256>>>(s->d1, W2, s->g2d, HH, 0, &s->m1, BB);
    k_mark<<<EBLK, 256>>>(s, ei, 2);
    k_compact<<<1, 512>>>(s, 2);
    k_aggb<<<NN, HH>>>(s, b2, 2);
    k_aggd<<<dim3(BB, 8), HH>>>(s, 2);
    k_statsA<<<8, 256>>>(s, 2);
    k_statsD<<<128, 256>>>(s, 2);
    k_fin23<<<1, 256>>>(s, g2, be2, 2);
    k_zb<<<NN, HH>>>(s, 2);
    k_d2<<<dim3(BB, 8), HH>>>(s);

    // layer 3
    k_gemm<<<dim3(8, 4), 256>>>(s->zb2, W3, s->g3b, HH, NN, nullptr, 0);
    k_gemm<<<dim3(GBIG, 4), 256>>>(s->d2, W3, s->g3d, HH, 0, &s->m2, BB);
    k_mark<<<EBLK, 256>>>(s, ei, 3);
    k_compact<<<1, 512>>>(s, 3);
    k_aggb<<<NN, HH>>>(s, b3, 3);
    k_aggd<<<dim3(BB, 8), HH>>>(s, 3);
    k_statsA<<<8, 256>>>(s, 3);
    k_statsD<<<128, 256>>>(s, 3);
    k_fin23<<<1, 256>>>(s, g3, be3, 3);

    k_out<<<dim3(NN, BB), HH>>>(s, (float*)d_out);
}

// round 3
// speedup vs baseline: 1.0635x; 1.0635x over previous
#include <cuda_runtime.h>
#include <math.h>

#define BB   128          // batch
#define NKG  500          // KG vertices
#define NN   502          // total nodes
#define DD   1024         // embed dim
#define HH   256          // hidden
#define EE   4000         // edges
#define NBTOT (BB*NN)     // 64256
#define ZROWS (NN + BB*NN)   // 64758 rows in fused [base; dep] buffers

// ---------------------------------------------------------------------------
// Scratch (single __device__ symbol)
// ---------------------------------------------------------------------------
struct __align__(16) Scratch {
    float hb[640*HH];                 // fused layer-1 GEMM out: rows 0..499 base, 500..627 sensor
    float a1[NN*HH], a2[NN*HH], a3[NN*HH];
    float zd1[(size_t)ZROWS*HH];      // [zb1(502 rows); d1(B*m1 rows)]
    float g2 [(size_t)ZROWS*HH];
    float zd2[(size_t)ZROWS*HH];
    float g3 [(size_t)ZROWS*HH];
    float dy2[(size_t)BB*NN*HH];
    float dy3[(size_t)BB*NN*HH];
    float csr_norm[EE];
    float c[NN], dinv[NN];
    float accA[3][HH], accAsq[3][HH], accD[3][HH], accDsq[3][HH], accAD[3][HH];
    float accS[HH], accS2[HH], accAc[HH];
    float sc[3][HH], sh[3][HH];
    int   csr_src[EE];
    int   off[NN+1];
    int   slot1[NN], slot2[NN], slot3[NN];
    int   list1[NN], list2[NN], list3[NN];
    int   m1, m2, m3;
    int   ctr[4];
};
__device__ Scratch S;

__device__ __forceinline__ float elu_f(float x) { return x > 0.f ? x : expm1f(x); }
__device__ __forceinline__ int clampn(int v) { return v < 0 ? 0 : (v >= NN ? NN - 1 : v); }

// ---------------------------------------------------------------------------
// init: zero hb + accumulators + counters
// ---------------------------------------------------------------------------
__global__ void k_init(Scratch* s) {
    int bb = blockIdx.x, t = threadIdx.x;
    if (bb < 640) {
        s->hb[(size_t)bb*HH + t] = 0.f;
    } else {
        for (int l = 0; l < 3; l++) {
            s->accA[l][t]=0.f; s->accAsq[l][t]=0.f;
            s->accD[l][t]=0.f; s->accDsq[l][t]=0.f; s->accAD[l][t]=0.f;
        }
        s->accS[t]=0.f; s->accS2[t]=0.f; s->accAc[t]=0.f;
        if (t < 4) s->ctr[t] = 0;
    }
}

// ---------------------------------------------------------------------------
// ALL graph topology in one block: count, scan, CSR, c, compactions 1-3
// ---------------------------------------------------------------------------
__global__ void k_graph(Scratch* s, const int* __restrict__ ei) {
    __shared__ int   cnt[NN];
    __shared__ int   sm[512];
    __shared__ float dsh[NN];
    __shared__ float cc[NN];
    __shared__ int   sl1[NN];
    __shared__ int   sl2[NN];
    __shared__ int   mk[NN];
    int t = threadIdx.x;

    if (t < NN) cnt[t] = 0;
    __syncthreads();
    for (int e = t; e < EE; e += 512) atomicAdd(&cnt[clampn(ei[EE + e])], 1);
    __syncthreads();

    int deg = (t < NN) ? cnt[t] : 0;
    float di = rsqrtf((float)(deg + 1));
    if (t < NN) { s->dinv[t] = di; dsh[t] = di; }

    // inclusive scan of degrees
    sm[t] = deg; __syncthreads();
    for (int d = 1; d < 512; d <<= 1) {
        int x = (t >= d) ? sm[t - d] : 0; __syncthreads();
        sm[t] += x; __syncthreads();
    }
    if (t < NN) s->off[t] = sm[t] - deg;
    if (t == 0) s->off[NN] = sm[NN - 1];
    if (t < NN) cnt[t] = 0;            // reuse as cursor
    __syncthreads();

    // CSR fill
    for (int e = t; e < EE; e += 512) {
        int src = clampn(ei[e]), dst = clampn(ei[EE + e]);
        int p = s->off[dst] + atomicAdd(&cnt[dst], 1);
        s->csr_src[p] = src;
        s->csr_norm[p] = dsh[src] * dsh[dst];
    }

    // c[n]: coefficient of hsens in layer-1 aggregate at node n
    if (t < NN) cc[t] = 0.f;
    __syncthreads();
    for (int e = t; e < EE; e += 512) {
        int src = clampn(ei[e]);
        if (src == NKG) {
            int dst = clampn(ei[EE + e]);
            atomicAdd(&cc[dst], dsh[NKG] * dsh[dst]);
        }
    }
    __syncthreads();
    if (t == NKG) cc[t] += dsh[NKG] * dsh[NKG];   // self loop at sensor node
    __syncthreads();
    if (t < NN) s->c[t] = cc[t];

    // compact 1: S1 = {n : c[n] > 0}
    int f = (t < NN) && (cc[t] > 0.f);
    sm[t] = f; __syncthreads();
    for (int d = 1; d < 512; d <<= 1) {
        int x = (t >= d) ? sm[t - d] : 0; __syncthreads();
        sm[t] += x; __syncthreads();
    }
    if (t < NN) {
        int sl = f ? sm[t] - 1 : -1;
        sl1[t] = sl; s->slot1[t] = sl;
        if (f) s->list1[sm[t] - 1] = t;
    }
    if (t == 0) s->m1 = sm[NN - 1];
    __syncthreads();

    // mark2 = S1 ∪ N(S1), compact 2
    if (t < NN) mk[t] = (sl1[t] >= 0) ? 1 : 0;
    __syncthreads();
    for (int e = t; e < EE; e += 512) {
        int src = clampn(ei[e]);
        if (sl1[src] >= 0) mk[clampn(ei[EE + e])] = 1;
    }
    __syncthreads();
    f = (t < NN) && mk[t];
    sm[t] = f; __syncthreads();
    for (int d = 1; d < 512; d <<= 1) {
        int x = (t >= d) ? sm[t - d] : 0; __syncthreads();
        sm[t] += x; __syncthreads();
    }
    if (t < NN) {
        int sl = f ? sm[t] - 1 : -1;
        sl2[t] = sl; s->slot2[t] = sl;
        if (f) s->list2[sm[t] - 1] = t;
    }
    if (t == 0) s->m2 = sm[NN - 1];
    __syncthreads();

    // mark3 = S2 ∪ N(S2), compact 3
    if (t < NN) mk[t] = (sl2[t] >= 0) ? 1 : 0;
    __syncthreads();
    for (int e = t; e < EE; e += 512) {
        int src = clampn(ei[e]);
        if (sl2[src] >= 0) mk[clampn(ei[EE + e])] = 1;
    }
    __syncthreads();
    f = (t < NN) && mk[t];
    sm[t] = f; __syncthreads();
    for (int d = 1; d < 512; d <<= 1) {
        int x = (t >= d) ? sm[t - d] : 0; __syncthreads();
        sm[t] += x; __syncthreads();
    }
    if (t < NN) {
        s->slot3[t] = f ? sm[t] - 1 : -1;
        if (f) s->list3[sm[t] - 1] = t;
    }
    if (t == 0) s->m3 = sm[NN - 1];
}

// ---------------------------------------------------------------------------
// layer-1 fused GEMM (base + sensor rows), split-K, atomic accumulate into hb
// grid (10, 4, 4): 64-row × 64-col tiles, K chunks of 256
// ---------------------------------------------------------------------------
__global__ void k_gemm1(const float* __restrict__ basev, const float* __restrict__ sensor,
                        const float* __restrict__ W, float* __restrict__ hb) {
    int rb = blockIdx.x * 64, cb = blockIdx.y * 64, kc = blockIdx.z * 256;
    __shared__ __align__(16) float As[16][64];
    __shared__ __align__(16) float Ws[16][64];
    int tid = threadIdx.x;
    int tm = (tid >> 4) << 2, tn = (tid & 15) << 2;
    int r  = tid >> 2,  kk = (tid & 3) << 2;
    int wr = tid >> 4,  wc = (tid & 15) << 2;
    float acc[4][4] = {};
    int row = rb + r;
    const float* Arow = (row < NKG) ? basev + (size_t)row * DD
                      : (row < NKG + BB) ? sensor + (size_t)(row - NKG) * DD : 0;
    for (int k0 = kc; k0 < kc + 256; k0 += 16) {
        float4 av = make_float4(0.f, 0.f, 0.f, 0.f);
        if (Arow) av = *(const float4*)(Arow + k0 + kk);
        As[kk][r] = av.x; As[kk+1][r] = av.y; As[kk+2][r] = av.z; As[kk+3][r] = av.w;
        *(float4*)&Ws[wr][wc] = *(const float4*)(W + (size_t)(k0 + wr) * HH + cb + wc);
        __syncthreads();
#pragma unroll
        for (int q = 0; q < 16; q++) {
            float4 bv = *(const float4*)&Ws[q][tn];
            float a0 = As[q][tm], a1 = As[q][tm+1], a2 = As[q][tm+2], a3 = As[q][tm+3];
            acc[0][0]+=a0*bv.x; acc[0][1]+=a0*bv.y; acc[0][2]+=a0*bv.z; acc[0][3]+=a0*bv.w;
            acc[1][0]+=a1*bv.x; acc[1][1]+=a1*bv.y; acc[1][2]+=a1*bv.z; acc[1][3]+=a1*bv.w;
            acc[2][0]+=a2*bv.x; acc[2][1]+=a2*bv.y; acc[2][2]+=a2*bv.z; acc[2][3]+=a2*bv.w;
            acc[3][0]+=a3*bv.x; acc[3][1]+=a3*bv.y; acc[3][2]+=a3*bv.z; acc[3][3]+=a3*bv.w;
        }
        __syncthreads();
    }
#pragma unroll
    for (int i = 0; i < 4; i++) {
        int orow = rb + tm + i;
        if (orow < NKG + BB) {
            float* p = hb + (size_t)orow * HH + cb + tn;
            atomicAdd(p+0, acc[i][0]); atomicAdd(p+1, acc[i][1]);
            atomicAdd(p+2, acc[i][2]); atomicAdd(p+3, acc[i][3]);
        }
    }
}

// ---------------------------------------------------------------------------
// generic GEMM: C[M,256] = A[M,K] @ W[K,256], M = Mbase + (*mptr)*mmul
// ---------------------------------------------------------------------------
__global__ void k_gemm(const float* __restrict__ A, const float* __restrict__ W,
                       float* __restrict__ C, int K, int Mbase,
                       const int* __restrict__ mptr, int mmul) {
    int M = Mbase + (mptr ? (*mptr) * mmul : 0);
    int rb = blockIdx.x * 64;
    if (rb >= M) return;
    int cb = blockIdx.y * 64;
    __shared__ __align__(16) float As[16][64];
    __shared__ __align__(16) float Ws[16][64];
    int tid = threadIdx.x;
    int tm = (tid >> 4) << 2, tn = (tid & 15) << 2;
    int r  = tid >> 2,  kk = (tid & 3) << 2;
    int wr = tid >> 4,  wc = (tid & 15) << 2;
    float acc[4][4] = {};
    for (int k0 = 0; k0 < K; k0 += 16) {
        float4 av = make_float4(0.f, 0.f, 0.f, 0.f);
        if (rb + r < M) av = *(const float4*)(A + (size_t)(rb + r) * K + k0 + kk);
        As[kk][r] = av.x; As[kk+1][r] = av.y; As[kk+2][r] = av.z; As[kk+3][r] = av.w;
        *(float4*)&Ws[wr][wc] = *(const float4*)(W + (size_t)(k0 + wr) * HH + cb + wc);
        __syncthreads();
#pragma unroll
        for (int q = 0; q < 16; q++) {
            float4 bv = *(const float4*)&Ws[q][tn];
            float a0 = As[q][tm], a1 = As[q][tm+1], a2 = As[q][tm+2], a3 = As[q][tm+3];
            acc[0][0]+=a0*bv.x; acc[0][1]+=a0*bv.y; acc[0][2]+=a0*bv.z; acc[0][3]+=a0*bv.w;
            acc[1][0]+=a1*bv.x; acc[1][1]+=a1*bv.y; acc[1][2]+=a1*bv.z; acc[1][3]+=a1*bv.w;
            acc[2][0]+=a2*bv.x; acc[2][1]+=a2*bv.y; acc[2][2]+=a2*bv.z; acc[2][3]+=a2*bv.w;
            acc[3][0]+=a3*bv.x; acc[3][1]+=a3*bv.y; acc[3][2]+=a3*bv.z; acc[3][3]+=a3*bv.w;
        }
        __syncthreads();
    }
#pragma unroll
    for (int i = 0; i < 4; i++) {
        int row = rb + tm + i;
        if (row < M)
            *(float4*)(C + (size_t)row * HH + cb + tn) =
                make_float4(acc[i][0], acc[i][1], acc[i][2], acc[i][3]);
    }
}

// ---------------------------------------------------------------------------
// layer-1 batch-independent aggregation
// ---------------------------------------------------------------------------
__global__ void k_agg1(Scratch* s, const float* __restrict__ b1) {
    int n = blockIdx.x, h = threadIdx.x;
    int e0 = s->off[n], e1 = s->off[n + 1];
    float acc = b1[h];
    for (int e = e0; e < e1; e++) {
        int src = s->csr_src[e];
        if (src < NKG) acc += s->csr_norm[e] * s->hb[(size_t)src * HH + h];
    }
    float di = s->dinv[n];
    if (n < NKG) acc += di * di * s->hb[(size_t)n * HH + h];
    s->a1[n * HH + h] = acc;
}

// ---------------------------------------------------------------------------
// layer-1 BN stats + finalize (last-ticket block)
// ---------------------------------------------------------------------------
__global__ void k_sf1(Scratch* s, const float* __restrict__ gamma,
                      const float* __restrict__ beta) {
    int h = threadIdx.x, bb = blockIdx.x;
    const float* hsens = s->hb + (size_t)NKG * HH;
    if (bb < 8) {
        float sA = 0.f, sA2 = 0.f, sAc = 0.f;
        for (int n = bb; n < NN; n += 8) {
            float A = s->a1[n * HH + h], cv = s->c[n];
            sA += A; sA2 += A * A; sAc += A * cv;
        }
        atomicAdd(&s->accA[0][h], sA);
        atomicAdd(&s->accAsq[0][h], sA2);
        atomicAdd(&s->accAc[h], sAc);
    } else {
        int k = bb - 8;
        float ss = 0.f, ss2 = 0.f;
        for (int b = k; b < BB; b += 2) {
            float v = hsens[(size_t)b * HH + h];
            ss += v; ss2 += v * v;
        }
        atomicAdd(&s->accS[h], ss);
        atomicAdd(&s->accS2[h], ss2);
    }
    __syncthreads();
    __shared__ int ticket;
    if (h == 0) { __threadfence(); ticket = atomicAdd(&s->ctr[0], 1); }
    __syncthreads();
    if (ticket == (int)gridDim.x - 1) {
        __threadfence();
        __shared__ float r1[256], r2[256];
        float lc = 0.f, lc2 = 0.f;
        for (int n = h; n < NN; n += 256) { float cv = s->c[n]; lc += cv; lc2 += cv * cv; }
        r1[h] = lc; r2[h] = lc2; __syncthreads();
        for (int d = 128; d > 0; d >>= 1) {
            if (h < d) { r1[h] += r1[h + d]; r2[h] += r2[h + d]; }
            __syncthreads();
        }
        float Ec  = r1[0] / NN, Ec2 = r2[0] / NN;
        float EA  = s->accA[0][h] / NN, EA2 = s->accAsq[0][h] / NN, EAc = s->accAc[h] / NN;
        float Es  = s->accS[h] / BB,  Es2 = s->accS2[h] / BB;
        float mu  = EA + Ec * Es;
        float ey2 = EA2 + 2.f * EAc * Es + Ec2 * Es2;
        float rstd = rsqrtf(ey2 - mu * mu + 1e-5f);
        float scv = rstd * gamma[h];
        s->sc[0][h] = scv; s->sh[0][h] = beta[h] - mu * scv;
    }
}

// ---------------------------------------------------------------------------
// BN+ELU materialization into fused [zb; d] buffer
// ---------------------------------------------------------------------------
__global__ void k_zd(Scratch* s, int layer) {
    int bb = blockIdx.x, h = threadIdx.x;
    if (layer == 1) {
        float scv = s->sc[0][h], shv = s->sh[0][h];
        if (bb < NN) {
            float v = (s->slot1[bb] >= 0) ? 0.f
                    : elu_f(s->a1[bb * HH + h] * scv + shv);
            s->zd1[(size_t)bb * HH + h] = v;
        } else {
            int b = bb - NN, m = s->m1;
            float sv = s->hb[(size_t)(NKG + b) * HH + h];
            for (int j = 0; j < m; j++) {
                int n = s->list1[j];
                float v = (s->a1[n * HH + h] + s->c[n] * sv) * scv + shv;
                s->zd1[(size_t)(NN + b * m + j) * HH + h] = elu_f(v);
            }
        }
    } else {
        float scv = s->sc[1][h], shv = s->sh[1][h];
        if (bb < NN) {
            float v = (s->slot2[bb] >= 0) ? 0.f
                    : elu_f(s->a2[bb * HH + h] * scv + shv);
            s->zd2[(size_t)bb * HH + h] = v;
        } else {
            int idx = bb - NN, b = idx >> 2, j0 = idx & 3;
            int m = s->m2;
            for (int j = j0; j < m; j += 4) {
                int n = s->list2[j];
                float v = (s->a2[n * HH + h] + s->dy2[(size_t)(b * m + j) * HH + h]) * scv + shv;
                s->zd2[(size_t)(NN + b * m + j) * HH + h] = elu_f(v);
            }
        }
    }
}

// ---------------------------------------------------------------------------
// fused base+dep aggregation for layers 2/3
// ---------------------------------------------------------------------------
__global__ void k_aggs(Scratch* s, const float* __restrict__ bias, int layer) {
    int bb = blockIdx.x, h = threadIdx.x;
    const float* g = (layer == 2) ? s->g2 : s->g3;
    if (bb < NN) {
        int n = bb;
        float di = s->dinv[n];
        float acc = bias[h] + di * di * g[(size_t)n * HH + h];
        int e1 = s->off[n + 1];
        for (int e = s->off[n]; e < e1; e++)
            acc += s->csr_norm[e] * g[(size_t)s->csr_src[e] * HH + h];
        ((layer == 2) ? s->a2 : s->a3)[n * HH + h] = acc;
    } else {
        int idx = bb - NN, b = idx >> 3, j0 = idx & 7;
        int m  = (layer == 2) ? s->m2 : s->m3;
        int mp = (layer == 2) ? s->m1 : s->m2;
        const int* list  = (layer == 2) ? s->list2 : s->list3;
        const int* pslot = (layer == 2) ? s->slot1 : s->slot2;
        float* dy = (layer == 2) ? s->dy2 : s->dy3;
        const float* gd = g + (size_t)NN * HH;
        for (int j = j0; j < m; j += 8) {
            int n = list[j];
            float acc = 0.f;
            int sl = pslot[n];
            float di = s->dinv[n];
            if (sl >= 0) acc += di * di * gd[(size_t)(b * mp + sl) * HH + h];
            int e1 = s->off[n + 1];
            for (int e = s->off[n]; e < e1; e++) {
                int sp = pslot[s->csr_src[e]];
                if (sp >= 0) acc += s->csr_norm[e] * gd[(size_t)(b * mp + sp) * HH + h];
            }
            dy[(size_t)(b * m + j) * HH + h] = acc;
        }
    }
}

// ---------------------------------------------------------------------------
// layers 2/3 BN stats + finalize (last-ticket block)
// ---------------------------------------------------------------------------
__global__ void k_sf23(Scratch* s, const float* __restrict__ gamma,
                       const float* __restrict__ beta, int layer) {
    int h = threadIdx.x, bb = blockIdx.x, L = layer - 1;
    const float* a = (layer == 2) ? s->a2 : s->a3;
    if (bb < 8) {
        float sA = 0.f, sA2 = 0.f;
        for (int n = bb; n < NN; n += 8) {
            float v = a[n * HH + h]; sA += v; sA2 += v * v;
        }
        atomicAdd(&s->accA[L][h], sA);
        atomicAdd(&s->accAsq[L][h], sA2);
    } else {
        int k = bb - 8;
        int m = (layer == 2) ? s->m2 : s->m3;
        const float* dy = (layer == 2) ? s->dy2 : s->dy3;
        const int* list = (layer == 2) ? s->list2 : s->list3;
        int R = BB * m;
        float sd = 0.f, sd2 = 0.f, sad = 0.f;
        for (int r = k; r < R; r += 128) {
            int j = r % m;
            float dv = dy[(size_t)r * HH + h];
            float A  = a[list[j] * HH + h];
            sd += dv; sd2 += dv * dv; sad += A * dv;
        }
        atomicAdd(&s->accD[L][h], sd);
        atomicAdd(&s->accDsq[L][h], sd2);
        atomicAdd(&s->accAD[L][h], sad);
    }
    __syncthreads();
    __shared__ int ticket;
    if (h == 0) { __threadfence(); ticket = atomicAdd(&s->ctr[L], 1); }
    __syncthreads();
    if (ticket == (int)gridDim.x - 1) {
        __threadfence();
        float mu  = (BB * s->accA[L][h] + s->accD[L][h]) * (1.f / NBTOT);
        float ey2 = (BB * s->accAsq[L][h] + 2.f * s->accAD[L][h] + s->accDsq[L][h]) * (1.f / NBTOT);
        float rstd = rsqrtf(ey2 - mu * mu + 1e-5f);
        float scv = rstd * gamma[h];
        s->sc[L][h] = scv; s->sh[L][h] = beta[h] - mu * scv;
    }
}

// ---------------------------------------------------------------------------
// final output: elu(bn3(a3 + dy3))
// ---------------------------------------------------------------------------
__global__ void k_out(Scratch* s, float* __restrict__ out) {
    int n = blockIdx.x, b = blockIdx.y, h = threadIdx.x;
    float v = s->a3[n * HH + h];
    int sl = s->slot3[n];
    if (sl >= 0) v += s->dy3[(size_t)(b * s->m3 + sl) * HH + h];
    v = v * s->sc[2][h] + s->sh[2][h];
    out[((size_t)b * NN + n) * HH + h] = elu_f(v);
}

// ---------------------------------------------------------------------------
// launch (14 kernels)
// ---------------------------------------------------------------------------
extern "C" void kernel_launch(void* const* d_in, const int* in_sizes, int n_in,
                              void* d_out, int out_size) {
    const float* sensor = (const float*)d_in[0];
    const float* basev  = (const float*)d_in[1];
    const int* ei       = (const int*)d_in[2];     // int32 (JAX x64 disabled)
    const float* W1 = (const float*)d_in[3];  const float* b1 = (const float*)d_in[4];
    const float* gm1 = (const float*)d_in[5]; const float* be1 = (const float*)d_in[6];
    const float* W2 = (const float*)d_in[7];  const float* b2 = (const float*)d_in[8];
    const float* gm2 = (const float*)d_in[9]; const float* be2 = (const float*)d_in[10];
    const float* W3 = (const float*)d_in[11]; const float* b3 = (const float*)d_in[12];
    const float* gm3 = (const float*)d_in[13];const float* be3 = (const float*)d_in[14];

    void* sp = nullptr;
    cudaGetSymbolAddress(&sp, S);
    Scratch* s = (Scratch*)sp;

    const int GBIG = (ZROWS + 63) / 64;    // 1012 row blocks upper bound

    k_init<<<641, 256>>>(s);
    k_graph<<<1, 512>>>(s, ei);
    k_gemm1<<<dim3(10, 4, 4), 256>>>(basev, sensor, W1, s->hb);
    k_agg1<<<NN, 256>>>(s, b1);
    k_sf1<<<10, 256>>>(s, gm1, be1);
    k_zd<<<NN + BB, 256>>>(s, 1);

    k_gemm<<<dim3(GBIG, 4), 256>>>(s->zd1, W2, s->g2, HH, NN, &s->m1, BB);
    k_aggs<<<NN + BB*8, 256>>>(s, b2, 2);
    k_sf23<<<136, 256>>>(s, gm2, be2, 2);
    k_zd<<<NN + BB*4, 256>>>(s, 2);

    k_gemm<<<dim3(GBIG, 4), 256>>>(s->zd2, W3, s->g3, HH, NN, &s->m2, BB);
    k_aggs<<<NN + BB*8, 256>>>(s, b3, 3);
    k_sf23<<<136, 256>>>(s, gm3, be3, 3);

    k_out<<<dim3(NN, BB), 256>>>(s, (float*)d_out);
}